// round 4
// baseline (speedup 1.0000x reference)
#include <cuda_runtime.h>
#include <cstdint>

// Problem shapes
#define NG   1024          // segments
#define R0   8192          // theta0 rows
#define C0   4096          // theta0 cols / obs0 cols / mapping1 cols / obs2 len
#define R1   4096          // theta1 rows / p1 len
#define C1   2048          // theta1 cols
#define MR   512           // mapping1 rows / obs1 len

#define PRE_GRID   544     // 512 p1 blocks + 32 count blocks
#define SEG_BLKS   2048    // 512 chunks (2 groups) x 4 col tiles
#define MAIN_GRID  (SEG_BLKS + 1024)

// Scratch (static device globals — zero-initialized at load; no allocation)
__device__ float  d_p1[R1];
__device__ float  d_p2[C0];
__device__ float  d_m1[MR];
__device__ int    d_cnt[NG];        // zeroed by scan tail each run
__device__ int    d_rowg[R0];
__device__ int    d_rowpos[R0];
__device__ int    d_rowlist[R0];
__device__ int    d_startg[NG + 1];
__device__ double d_lossA;
__device__ int    d_sync0;          // k_pre completion counter (self-reset)
__device__ int    d_sync1;          // k_main completion counter (self-reset)

// ---------------------------------------------------------------------------
__device__ __forceinline__ float block_reduce_sum(float v) {
    __shared__ float s[32];
    int lane = threadIdx.x & 31, w = threadIdx.x >> 5;
    #pragma unroll
    for (int o = 16; o; o >>= 1) v += __shfl_down_sync(0xffffffffu, v, o);
    if (!lane) s[w] = v;
    __syncthreads();
    int nw = (blockDim.x + 31) >> 5;
    v = (threadIdx.x < nw) ? s[threadIdx.x] : 0.f;
    if (w == 0) {
        #pragma unroll
        for (int o = 16; o; o >>= 1) v += __shfl_down_sync(0xffffffffu, v, o);
    }
    return v;  // valid in thread 0
}

// ---------------------------------------------------------------------------
// Kernel 1: blocks [0,512): p1[r] = sum_c exp(theta1[r,c])  (warp per row)
//           blocks [512,544): histogram counts + (g,pos) per row + zeroing.
// LAST finishing block: scan counts -> d_startg, scatter d_rowlist. No extra
// launch for the serial scan.
__global__ void __launch_bounds__(256) k_pre(
        const float* __restrict__ theta1,
        const int*   __restrict__ idx_raw) {
    const int t = threadIdx.x;

    if (blockIdx.x < 512) {
        const int warp = t >> 5, lane = t & 31;
        const int row  = blockIdx.x * 8 + warp;
        const float* base = theta1 + (size_t)row * C1;
        float acc = 0.f;
        #pragma unroll 4
        for (int c = lane * 4; c < C1; c += 128) {
            float4 x = __ldcs(reinterpret_cast<const float4*>(base + c));
            acc += __expf(x.x) + __expf(x.y) + __expf(x.z) + __expf(x.w);
        }
        #pragma unroll
        for (int o = 16; o; o >>= 1) acc += __shfl_down_sync(0xffffffffu, acc, o);
        if (!lane) d_p1[row] = acc;
    } else {
        const int b = blockIdx.x - 512;          // 0..31

        // dtype detect on fixed window of pair hi-words [0,512): int64 with
        // values<1024 -> all zero; int32 -> random ids, P(all zero)~0.
        int w = idx_raw[2 * t + 1] | idx_raw[2 * (t + 256) + 1];
        int any = __syncthreads_or(w);
        const bool is64 = (any == 0);

        const int i = b * 256 + t;               // row index, covers 8192
        const int g = is64 ? idx_raw[2 * i] : idx_raw[i];
        const int pos = atomicAdd(&d_cnt[g], 1);
        d_rowg[i]   = g;
        d_rowpos[i] = pos;

        if (t < 128) d_p2[b * 128 + t] = 0.f;
        if (b == 0) {
            if (t == 0) d_lossA = 0.0;
            d_m1[t] = 0.f;
            d_m1[t + 256] = 0.f;
        }
    }

    // ---- completion detection: last block does scan + scatter ----
    __shared__ int s_last;
    __threadfence();
    __syncthreads();
    if (t == 0) s_last = (atomicAdd(&d_sync0, 1) == PRE_GRID - 1);
    __syncthreads();
    if (!s_last) return;

    __shared__ int s_base[NG];
    __shared__ int s_wtot[8];
    // each thread owns 4 consecutive counts
    int c0v[4], tsum = 0;
    #pragma unroll
    for (int k = 0; k < 4; k++) {
        c0v[k] = d_cnt[4 * t + k];
        d_cnt[4 * t + k] = 0;                    // reset for next replay
        tsum += c0v[k];
    }
    // inclusive shfl scan of per-thread sums within warp
    const int lane = t & 31, wp = t >> 5;
    int v = tsum;
    #pragma unroll
    for (int o = 1; o < 32; o <<= 1) {
        int u = __shfl_up_sync(0xffffffffu, v, o);
        if (lane >= o) v += u;
    }
    if (lane == 31) s_wtot[wp] = v;
    __syncthreads();
    if (t == 0) {
        int a = 0;
        #pragma unroll
        for (int k = 0; k < 8; k++) { int x = s_wtot[k]; s_wtot[k] = a; a += x; }
        d_startg[NG] = a;                         // == R0
    }
    __syncthreads();
    int run = v - tsum + s_wtot[wp];              // exclusive prefix, first elem
    #pragma unroll
    for (int k = 0; k < 4; k++) {
        s_base[4 * t + k] = run;
        d_startg[4 * t + k] = run;
        run += c0v[k];
    }
    __syncthreads();
    // scatter rows into group-contiguous order
    #pragma unroll 4
    for (int i = t; i < R0; i += 256)
        d_rowlist[s_base[d_rowg[i]] + d_rowpos[i]] = i;
    if (t == 0) d_sync0 = 0;                      // reset for next replay
}

// ---------------------------------------------------------------------------
// Kernel 2 (hot): blocks [0,2048): segment-sum of exp(theta0) + fused loss_a
// + p2 accumulation (2 groups x 1024-col tile per block, MLP=4 inner loads).
// Blocks [2048,3072): m1 = mapping1 @ p1 (GEMV strips).
// LAST finishing block: loss_b + loss_c + final combine -> out[0].
__global__ void __launch_bounds__(256) k_main(
        const float* __restrict__ theta0,
        const float* __restrict__ obs0,
        const float* __restrict__ mapping1,
        const float* __restrict__ obs1,
        const float* __restrict__ obs2,
        float* __restrict__ out) {
    const int t = threadIdx.x;

    if (blockIdx.x < SEG_BLKS) {
        const int chunk = blockIdx.x >> 2;       // 0..511
        const int tile  = blockIdx.x & 3;        // 0..3
        const int col   = tile * 1024 + t * 4;

        float4 p2l  = make_float4(0.f, 0.f, 0.f, 0.f);
        float  lossl = 0.f;

        #pragma unroll 1
        for (int gi = 0; gi < 2; gi++) {
            const int g = chunk * 2 + gi;
            const int s = d_startg[g], e = d_startg[g + 1];

            float4 acc = make_float4(0.f, 0.f, 0.f, 0.f);
            int r = s;
            // 4 independent loads per body -> MLP 4
            for (; r + 4 <= e; r += 4) {
                const int i0 = d_rowlist[r + 0], i1 = d_rowlist[r + 1];
                const int i2 = d_rowlist[r + 2], i3 = d_rowlist[r + 3];
                float4 a = __ldcs(reinterpret_cast<const float4*>(theta0 + (size_t)i0 * C0 + col));
                float4 bb= __ldcs(reinterpret_cast<const float4*>(theta0 + (size_t)i1 * C0 + col));
                float4 c = __ldcs(reinterpret_cast<const float4*>(theta0 + (size_t)i2 * C0 + col));
                float4 d = __ldcs(reinterpret_cast<const float4*>(theta0 + (size_t)i3 * C0 + col));
                acc.x += __expf(a.x) + __expf(bb.x) + __expf(c.x) + __expf(d.x);
                acc.y += __expf(a.y) + __expf(bb.y) + __expf(c.y) + __expf(d.y);
                acc.z += __expf(a.z) + __expf(bb.z) + __expf(c.z) + __expf(d.z);
                acc.w += __expf(a.w) + __expf(bb.w) + __expf(c.w) + __expf(d.w);
            }
            for (; r < e; r++) {
                const int i0 = d_rowlist[r];
                float4 a = __ldcs(reinterpret_cast<const float4*>(theta0 + (size_t)i0 * C0 + col));
                acc.x += __expf(a.x); acc.y += __expf(a.y);
                acc.z += __expf(a.z); acc.w += __expf(a.w);
            }
            p2l.x += acc.x; p2l.y += acc.y; p2l.z += acc.z; p2l.w += acc.w;

            const float4 o = __ldcs(reinterpret_cast<const float4*>(
                obs0 + (size_t)g * C0 + col));
            float dx = o.x - acc.x, dy = o.y - acc.y;
            float dz = o.z - acc.z, dw = o.w - acc.w;
            lossl += dx * dx + dy * dy + dz * dz + dw * dw;
        }

        atomicAdd(&d_p2[col + 0], p2l.x);
        atomicAdd(&d_p2[col + 1], p2l.y);
        atomicAdd(&d_p2[col + 2], p2l.z);
        atomicAdd(&d_p2[col + 3], p2l.w);

        float l = block_reduce_sum(lossl);
        if (t == 0) atomicAdd(&d_lossA, (double)l);
    } else {
        // GEMV: 512 rows x 2 strips (2048 cols each), 2 float4 per thread
        const int b     = blockIdx.x - SEG_BLKS; // 0..1023
        const int row   = b >> 1;
        const int strip = b & 1;
        const int c0    = strip * 2048;
        const float* mrow = mapping1 + (size_t)row * C0 + c0;
        const int t4 = t * 4;

        float4 ma = __ldcs(reinterpret_cast<const float4*>(mrow + t4));
        float4 pa = *reinterpret_cast<const float4*>(d_p1 + c0 + t4);
        float4 mb = __ldcs(reinterpret_cast<const float4*>(mrow + 1024 + t4));
        float4 pb = *reinterpret_cast<const float4*>(d_p1 + c0 + 1024 + t4);

        float acc = ma.x * pa.x + ma.y * pa.y + ma.z * pa.z + ma.w * pa.w
                  + mb.x * pb.x + mb.y * pb.y + mb.z * pb.z + mb.w * pb.w;
        acc = block_reduce_sum(acc);
        if (t == 0) atomicAdd(&d_m1[row], acc);
    }

    // ---- completion detection: last block computes final losses ----
    __shared__ int s_last;
    __threadfence();
    __syncthreads();
    if (t == 0) s_last = (atomicAdd(&d_sync1, 1) == MAIN_GRID - 1);
    __syncthreads();
    if (!s_last) return;

    // loss_b: 512 elems, 2 per thread
    float lb = 0.f;
    {
        float d0 = obs1[t]       - d_m1[t];
        float d1 = obs1[t + 256] - d_m1[t + 256];
        lb = d0 * d0 + d1 * d1;
    }
    lb = block_reduce_sum(lb);
    __shared__ float s_lb;
    if (t == 0) s_lb = lb;
    __syncthreads();

    // loss_c: 4096 elems, float4 x 4 per thread
    float lc = 0.f;
    #pragma unroll
    for (int k = 0; k < 4; k++) {
        const int c = k * 1024 + t * 4;
        float4 o = *reinterpret_cast<const float4*>(obs2 + c);
        float4 p = *reinterpret_cast<const float4*>(d_p2 + c);
        float dx = o.x - p.x, dy = o.y - p.y, dz = o.z - p.z, dw = o.w - p.w;
        lc += dx * dx + dy * dy + dz * dz + dw * dw;
    }
    lc = block_reduce_sum(lc);

    if (t == 0) {
        double la  = d_lossA / ((double)NG * (double)C0);
        double lbm = (double)s_lb / (double)MR;
        double lcm = 0.5 * (double)lc / (double)C0;
        out[0] = (float)((la + lbm + lcm) / 3.0);
        d_sync1 = 0;                              // reset for next replay
    }
}

// ---------------------------------------------------------------------------
extern "C" void kernel_launch(void* const* d_in, const int* in_sizes, int n_in,
                              void* d_out, int out_size) {
    const float* theta0   = (const float*)d_in[0];
    const float* theta1   = (const float*)d_in[1];
    const float* obs0     = (const float*)d_in[2];
    const float* obs1     = (const float*)d_in[3];
    const float* obs2     = (const float*)d_in[4];
    const int*   idx_raw  = (const int*)d_in[5];   // int32 or int64 (detected)
    const float* mapping1 = (const float*)d_in[6];
    float* out = (float*)d_out;

    k_pre <<<PRE_GRID, 256>>>(theta1, idx_raw);
    k_main<<<MAIN_GRID, 256>>>(theta0, obs0, mapping1, obs1, obs2, out);
}